// round 11
// baseline (speedup 1.0000x reference)
#include <cuda_runtime.h>

// PCEN: smooth[t] = 0.975*smooth[t-1] + 0.025*x[t], smooth[0]=x[0]
//       out = (x / (smooth+1e-6)^0.98 + 2)^0.5 - 2^0.5
//
// Exact warp-cooperative scan: one warp owns one full row (T=4096),
// 16 steps of 256 elements. Each lane folds 8 consecutive elements
// (two float4 loads, Horner with decay 0.975) into one affine offset,
// a 5-round Kogge-Stone shuffle scan (decay 0.975^8 per lane hop)
// composes across lanes, and the cross-step serial chain is ONE FMA
// (carry' = 0.975^256*carry + p31). vs the 49.5us version this halves
// the SHFL count and scan-chain serialization per row (scan every 256
// elements instead of 128). No SMEM, no barriers, exact (no lookback).

namespace {

constexpr int T_LEN = 4096;
constexpr int WPB   = 8;              // warps per block
constexpr int STEP  = 256;            // elements per warp-step
constexpr int NSTEP = T_LEN / STEP;   // 16

constexpr float A1 = 0.975f;
constexpr float S  = 0.025f;
constexpr float C1  = A1 * A1;             // 0.975^2
constexpr float H   = C1 * C1 * C1 * C1;   // 0.975^8  (lane hop)
constexpr float H2  = H * H;               // ^16
constexpr float H4  = H2 * H2;             // ^32
constexpr float H8  = H4 * H4;             // ^64
constexpr float H16 = H8 * H8;             // ^128
constexpr float H32 = H16 * H16;           // ^256 (step hop)

__device__ __forceinline__ float pcen_pt(float xv, float sm) {
    float l = __log2f(sm + 1e-6f);                // MUFU.LG2
    float g = exp2f(-0.98f * l);                  // MUFU.EX2
    float v = fmaf(xv, g, 2.0f);
    return rsqrtf(v) * v - 1.41421356237309515f;  // MUFU.RSQ; v >= 2
}

__global__ __launch_bounds__(WPB * 32)
void pcen_kernel(const float* __restrict__ x, float* __restrict__ out,
                 int nrows) {
    const int lane = threadIdx.x & 31;
    const int row  = blockIdx.x * WPB + (threadIdx.x >> 5);
    if (row >= nrows) return;

    const float4* __restrict__ xr =
        reinterpret_cast<const float4*>(x + (size_t)row * T_LEN) + 2 * lane;
    float4* __restrict__ orow =
        reinterpret_cast<float4*>(out + (size_t)row * T_LEN) + 2 * lane;

    // Al = H^lane via binary expansion (compile-time constants)
    float Al = 1.0f;
    if (lane & 1)  Al *= H;
    if (lane & 2)  Al *= H2;
    if (lane & 4)  Al *= H4;
    if (lane & 8)  Al *= H8;
    if (lane & 16) Al *= H16;

    const unsigned FULL = 0xffffffffu;

    float4 va = xr[0];
    float4 vb = xr[1];
    float carry = __shfl_sync(FULL, va.x, 0);  // fixed point: smooth[0] = x[0]

    #pragma unroll 2
    for (int k = 0; k < NSTEP; ++k) {
        float4 na = va, nb = vb;
        if (k + 1 < NSTEP) {
            na = xr[(k + 1) * (STEP / 4)];
            nb = xr[(k + 1) * (STEP / 4) + 1];
        }

        // lane-local affine offset over 8 elems (Horner, decay A1)
        float b = fmaf(A1, va.x, va.y);
        b = fmaf(A1, b, va.z);
        b = fmaf(A1, b, va.w);
        b = fmaf(A1, b, vb.x);
        b = fmaf(A1, b, vb.y);
        b = fmaf(A1, b, vb.z);
        b = fmaf(A1, b, vb.w);
        b *= S;

        // Kogge-Stone inclusive scan, decay H per lane hop
        float p = b, tt;
        tt = __shfl_up_sync(FULL, p, 1);  if (lane >= 1)  p = fmaf(H,   tt, p);
        tt = __shfl_up_sync(FULL, p, 2);  if (lane >= 2)  p = fmaf(H2,  tt, p);
        tt = __shfl_up_sync(FULL, p, 4);  if (lane >= 4)  p = fmaf(H4,  tt, p);
        tt = __shfl_up_sync(FULL, p, 8);  if (lane >= 8)  p = fmaf(H8,  tt, p);
        tt = __shfl_up_sync(FULL, p, 16); if (lane >= 16) p = fmaf(H16, tt, p);

        float pprev = __shfl_up_sync(FULL, p, 1);
        if (lane == 0) pprev = 0.0f;
        float p31 = __shfl_sync(FULL, p, 31);

        float s_in = fmaf(Al, carry, pprev);   // state entering this lane
        carry = fmaf(H32, carry, p31);         // serial chain: ONE FMA per step

        // first half: reconstruct + transform + store, frees va early
        float sm0 = fmaf(A1, s_in, S * va.x);
        float sm1 = fmaf(A1, sm0,  S * va.y);
        float sm2 = fmaf(A1, sm1,  S * va.z);
        float sm3 = fmaf(A1, sm2,  S * va.w);
        float4 o;
        o.x = pcen_pt(va.x, sm0);
        o.y = pcen_pt(va.y, sm1);
        o.z = pcen_pt(va.z, sm2);
        o.w = pcen_pt(va.w, sm3);
        __stcs(&orow[k * (STEP / 4)], o);

        // second half
        float sm4 = fmaf(A1, sm3, S * vb.x);
        float sm5 = fmaf(A1, sm4, S * vb.y);
        float sm6 = fmaf(A1, sm5, S * vb.z);
        float sm7 = fmaf(A1, sm6, S * vb.w);
        o.x = pcen_pt(vb.x, sm4);
        o.y = pcen_pt(vb.y, sm5);
        o.z = pcen_pt(vb.z, sm6);
        o.w = pcen_pt(vb.w, sm7);
        __stcs(&orow[k * (STEP / 4) + 1], o);

        va = na; vb = nb;
    }
}

}  // namespace

extern "C" void kernel_launch(void* const* d_in, const int* in_sizes, int n_in,
                              void* d_out, int out_size) {
    const float* x = (const float*)d_in[0];
    float* out = (float*)d_out;
    int nrows = in_sizes[0] / T_LEN;            // 8192 warps, one per row
    int blocks = (nrows + WPB - 1) / WPB;       // 1024 blocks
    pcen_kernel<<<blocks, WPB * 32>>>(x, out, nrows);
}

// round 12
// speedup vs baseline: 1.3527x; 1.3527x over previous
#include <cuda_runtime.h>

// PCEN: smooth[t] = 0.975*smooth[t-1] + 0.025*x[t], smooth[0]=x[0]
//       out = (x / (smooth+1e-6)^0.98 + 2)^0.5 - 2^0.5
//
// Exact warp-cooperative scan (R10 structure, best known): one warp owns
// one full row, 32 steps of 128 elements, lane-contiguous float4 I/O
// (512B per warp request). Per step: lane-local Horner fold, 5-round
// Kogge-Stone shuffle scan, 4-smooth reconstruct, PCEN, streaming store.
// Serial cross-step chain is ONE FMA. Changes vs R10 (49.2us):
//   - explicit 2-deep prefetch ring (>=2 LDGs in flight per warp, longer
//     read runs at the memory controller)
//   - __ldcs evict-first loads (no reuse; keep L2 for the write stream)

namespace {

constexpr int T_LEN = 4096;
constexpr int WPB   = 8;              // warps per block
constexpr int STEP  = 128;            // elements per warp-step
constexpr int NSTEP = T_LEN / STEP;   // 32

constexpr float A1 = 0.975f;
constexpr float S  = 0.025f;
constexpr float C1  = A1 * A1 * A1 * A1;   // 0.975^4
constexpr float C2  = C1 * C1;             // ^8
constexpr float C4  = C2 * C2;             // ^16
constexpr float C8  = C4 * C4;             // ^32
constexpr float C16 = C8 * C8;             // ^64
constexpr float C32 = C16 * C16;           // ^128

__device__ __forceinline__ float pcen_pt(float xv, float sm) {
    float l = __log2f(sm + 1e-6f);                // MUFU.LG2
    float g = exp2f(-0.98f * l);                  // MUFU.EX2
    float v = fmaf(xv, g, 2.0f);
    return rsqrtf(v) * v - 1.41421356237309515f;  // MUFU.RSQ; v >= 2
}

__global__ __launch_bounds__(WPB * 32)
void pcen_kernel(const float* __restrict__ x, float* __restrict__ out,
                 int nrows) {
    const int lane = threadIdx.x & 31;
    const int row  = blockIdx.x * WPB + (threadIdx.x >> 5);
    if (row >= nrows) return;

    const float4* __restrict__ xr =
        reinterpret_cast<const float4*>(x + (size_t)row * T_LEN) + lane;
    float4* __restrict__ orow =
        reinterpret_cast<float4*>(out + (size_t)row * T_LEN) + lane;

    // Al = C1^lane via binary expansion (compile-time constants)
    float Al = 1.0f;
    if (lane & 1)  Al *= C1;
    if (lane & 2)  Al *= C2;
    if (lane & 4)  Al *= C4;
    if (lane & 8)  Al *= C8;
    if (lane & 16) Al *= C16;

    const unsigned FULL = 0xffffffffu;

    // 2-deep prefetch ring
    float4 v0 = __ldcs(&xr[0]);
    float4 v1 = __ldcs(&xr[STEP / 4]);
    float carry = __shfl_sync(FULL, v0.x, 0);  // fixed point: smooth[0] = x[0]

    #pragma unroll 4
    for (int k = 0; k < NSTEP; ++k) {
        float4 v = v0;
        v0 = v1;
        if (k + 2 < NSTEP) v1 = __ldcs(&xr[(k + 2) * (STEP / 4)]);

        // lane-local affine offset: b = S*(A1^3 x0 + A1^2 x1 + A1 x2 + x3)
        float b = fmaf(A1, v.x, v.y);
        b = fmaf(A1, b, v.z);
        b = fmaf(A1, b, v.w);
        b *= S;

        // Kogge-Stone inclusive scan with decay C1 per lane-hop
        float p = b, tt;
        tt = __shfl_up_sync(FULL, p, 1);  if (lane >= 1)  p = fmaf(C1, tt, p);
        tt = __shfl_up_sync(FULL, p, 2);  if (lane >= 2)  p = fmaf(C2, tt, p);
        tt = __shfl_up_sync(FULL, p, 4);  if (lane >= 4)  p = fmaf(C4, tt, p);
        tt = __shfl_up_sync(FULL, p, 8);  if (lane >= 8)  p = fmaf(C8, tt, p);
        tt = __shfl_up_sync(FULL, p, 16); if (lane >= 16) p = fmaf(C16, tt, p);

        float pprev = __shfl_up_sync(FULL, p, 1);
        if (lane == 0) pprev = 0.0f;
        float p31 = __shfl_sync(FULL, p, 31);

        float s_in = fmaf(Al, carry, pprev);   // state entering this lane
        carry = fmaf(C32, carry, p31);         // serial chain: ONE FMA per step

        float sm0 = fmaf(A1, s_in, S * v.x);
        float sm1 = fmaf(A1, sm0,  S * v.y);
        float sm2 = fmaf(A1, sm1,  S * v.z);
        float sm3 = fmaf(A1, sm2,  S * v.w);
        float4 o;
        o.x = pcen_pt(v.x, sm0);
        o.y = pcen_pt(v.y, sm1);
        o.z = pcen_pt(v.z, sm2);
        o.w = pcen_pt(v.w, sm3);
        __stcs(&orow[k * (STEP / 4)], o);
    }
}

}  // namespace

extern "C" void kernel_launch(void* const* d_in, const int* in_sizes, int n_in,
                              void* d_out, int out_size) {
    const float* x = (const float*)d_in[0];
    float* out = (float*)d_out;
    int nrows = in_sizes[0] / T_LEN;            // 8192 warps, one per row
    int blocks = (nrows + WPB - 1) / WPB;       // 1024 blocks
    pcen_kernel<<<blocks, WPB * 32>>>(x, out, nrows);
}

// round 13
// speedup vs baseline: 1.5410x; 1.1391x over previous
#include <cuda_runtime.h>

// PCEN: smooth[t] = 0.975*smooth[t-1] + 0.025*x[t], smooth[0]=x[0]
//       out = (x / (smooth+1e-6)^0.98 + 2)^0.5 - 2^0.5
//
// Exact warp-cooperative scan (R10 structure): one warp owns one full row,
// 32 steps of 128 elements, lane-contiguous float4 I/O (512B/warp request).
// Per step: lane-local Horner fold, 5-round Kogge-Stone shuffle scan,
// 4-smooth reconstruct, PCEN, streaming store. Serial cross-step chain is
// ONE FMA (carry' = 0.975^128*carry + p31). Single change vs R10 (49.2us):
// #pragma unroll 8 (was 4) so ptxas can front-batch up to 8 independent
// LDG.128s per warp (higher MLP -> less exposed DRAM latency). The guarded
// software-prefetch form is kept verbatim: loads of different iterations
// are independent (no serialized register ring, the R12 mistake).

namespace {

constexpr int T_LEN = 4096;
constexpr int WPB   = 8;              // warps per block
constexpr int STEP  = 128;            // elements per warp-step
constexpr int NSTEP = T_LEN / STEP;   // 32

constexpr float A1 = 0.975f;
constexpr float S  = 0.025f;
constexpr float C1  = A1 * A1 * A1 * A1;   // 0.975^4
constexpr float C2  = C1 * C1;             // ^8
constexpr float C4  = C2 * C2;             // ^16
constexpr float C8  = C4 * C4;             // ^32
constexpr float C16 = C8 * C8;             // ^64
constexpr float C32 = C16 * C16;           // ^128

__device__ __forceinline__ float pcen_pt(float xv, float sm) {
    float l = __log2f(sm + 1e-6f);                // MUFU.LG2
    float g = exp2f(-0.98f * l);                  // MUFU.EX2
    float v = fmaf(xv, g, 2.0f);
    return rsqrtf(v) * v - 1.41421356237309515f;  // MUFU.RSQ; v >= 2
}

__global__ __launch_bounds__(WPB * 32)
void pcen_kernel(const float* __restrict__ x, float* __restrict__ out,
                 int nrows) {
    const int lane = threadIdx.x & 31;
    const int row  = blockIdx.x * WPB + (threadIdx.x >> 5);
    if (row >= nrows) return;

    const float4* __restrict__ xr =
        reinterpret_cast<const float4*>(x + (size_t)row * T_LEN) + lane;
    float4* __restrict__ orow =
        reinterpret_cast<float4*>(out + (size_t)row * T_LEN) + lane;

    // Al = C1^lane via binary expansion (compile-time constants)
    float Al = 1.0f;
    if (lane & 1)  Al *= C1;
    if (lane & 2)  Al *= C2;
    if (lane & 4)  Al *= C4;
    if (lane & 8)  Al *= C8;
    if (lane & 16) Al *= C16;

    const unsigned FULL = 0xffffffffu;

    float4 v = xr[0];
    float carry = __shfl_sync(FULL, v.x, 0);   // fixed point: smooth[0] = x[0]

    #pragma unroll 8
    for (int k = 0; k < NSTEP; ++k) {
        float4 vn = v;
        if (k + 1 < NSTEP) vn = xr[(k + 1) * (STEP / 4)];

        // lane-local affine offset: b = S*(A1^3 x0 + A1^2 x1 + A1 x2 + x3)
        float b = fmaf(A1, v.x, v.y);
        b = fmaf(A1, b, v.z);
        b = fmaf(A1, b, v.w);
        b *= S;

        // Kogge-Stone inclusive scan with decay C1 per lane-hop
        float p = b, tt;
        tt = __shfl_up_sync(FULL, p, 1);  if (lane >= 1)  p = fmaf(C1, tt, p);
        tt = __shfl_up_sync(FULL, p, 2);  if (lane >= 2)  p = fmaf(C2, tt, p);
        tt = __shfl_up_sync(FULL, p, 4);  if (lane >= 4)  p = fmaf(C4, tt, p);
        tt = __shfl_up_sync(FULL, p, 8);  if (lane >= 8)  p = fmaf(C8, tt, p);
        tt = __shfl_up_sync(FULL, p, 16); if (lane >= 16) p = fmaf(C16, tt, p);

        float pprev = __shfl_up_sync(FULL, p, 1);
        if (lane == 0) pprev = 0.0f;
        float p31 = __shfl_sync(FULL, p, 31);

        float s_in = fmaf(Al, carry, pprev);   // state entering this lane
        carry = fmaf(C32, carry, p31);         // serial chain: ONE FMA per step

        float sm0 = fmaf(A1, s_in, S * v.x);
        float sm1 = fmaf(A1, sm0,  S * v.y);
        float sm2 = fmaf(A1, sm1,  S * v.z);
        float sm3 = fmaf(A1, sm2,  S * v.w);
        float4 o;
        o.x = pcen_pt(v.x, sm0);
        o.y = pcen_pt(v.y, sm1);
        o.z = pcen_pt(v.z, sm2);
        o.w = pcen_pt(v.w, sm3);
        __stcs(&orow[k * (STEP / 4)], o);

        v = vn;
    }
}

}  // namespace

extern "C" void kernel_launch(void* const* d_in, const int* in_sizes, int n_in,
                              void* d_out, int out_size) {
    const float* x = (const float*)d_in[0];
    float* out = (float*)d_out;
    int nrows = in_sizes[0] / T_LEN;            // 8192 warps, one per row
    int blocks = (nrows + WPB - 1) / WPB;       // 1024 blocks
    pcen_kernel<<<blocks, WPB * 32>>>(x, out, nrows);
}